// round 1
// baseline (speedup 1.0000x reference)
#include <cuda_runtime.h>
#include <cstdint>

static constexpr int B = 4, S = 2048, D = 1024, H = 16, HD = 64;
static constexpr int M = B * S;  // 8192

// Scratch (allocation-free: __device__ globals)
__device__ float g_q[(size_t)B * H * S * HD];
__device__ float g_k[(size_t)B * H * S * HD];
__device__ float g_v[(size_t)B * H * S * HD];
__device__ float g_att[(size_t)B * S * D];
__device__ unsigned char g_qmask[B * S];
__device__ int g_sig;

// ---------------- mask dtype canonicalization ----------------
__global__ void k_init_sig() { g_sig = 0; }

__global__ void k_detect(const unsigned char* __restrict__ p) {
    int q = blockIdx.x * blockDim.x + threadIdx.x;
    if (q < B * S) {
        if (p[q] != 0) atomicOr(&g_sig, 1 << (q & 3));
    }
}

// bit1 set  -> raw uint8 bool
// bit2 set  -> float32 0.0/1.0
// else      -> int32 0/1
__global__ void k_convert(const void* __restrict__ p) {
    int q = blockIdx.x * blockDim.x + threadIdx.x;
    if (q >= B * S) return;
    int sig = g_sig;
    bool m;
    if (sig & 0x2)      m = ((const unsigned char*)p)[q] != 0;
    else if (sig & 0x4) m = ((const float*)p)[q] != 0.0f;
    else                m = ((const int*)p)[q] != 0;
    g_qmask[q] = m ? 1 : 0;
}

// ---------------- tiled SGEMM: C[M,N] = A[M,K] @ W[K,N] + bias ----------------
// layout 0: C row-major [M,N]   (final output)
// layout 1: scatter into [B,H,S,HD]  (QKV)
__global__ void __launch_bounds__(256) k_gemm(const float* __restrict__ A,
                                              const float* __restrict__ W,
                                              const float* __restrict__ bias,
                                              float* __restrict__ C,
                                              int layout)
{
    constexpr int N = 1024, K = 1024;
    __shared__ float As[8][128];
    __shared__ float Bs[8][128];
    const int t = threadIdx.x;
    const int tx = t & 15, ty = t >> 4;
    const int bx = blockIdx.x, by = blockIdx.y;

    const int arow = t >> 1, ac4 = (t & 1) * 4;
    const int brow = t >> 5, bc4 = (t & 31) * 4;
    const float* Ap = A + (size_t)(by * 128 + arow) * K + ac4;
    const float* Wp = W + (size_t)brow * N + bx * 128 + bc4;

    float acc[8][8];
    #pragma unroll
    for (int i = 0; i < 8; ++i)
        #pragma unroll
        for (int j = 0; j < 8; ++j) acc[i][j] = 0.f;

    for (int kb = 0; kb < K; kb += 8) {
        float4 av = *(const float4*)(Ap + kb);
        As[ac4 + 0][arow] = av.x;
        As[ac4 + 1][arow] = av.y;
        As[ac4 + 2][arow] = av.z;
        As[ac4 + 3][arow] = av.w;
        *(float4*)&Bs[brow][bc4] = *(const float4*)(Wp + (size_t)kb * N);
        __syncthreads();
        #pragma unroll
        for (int kk = 0; kk < 8; ++kk) {
            float a[8], bb[8];
            *(float4*)(a)     = *(const float4*)&As[kk][ty * 4];
            *(float4*)(a + 4) = *(const float4*)&As[kk][64 + ty * 4];
            *(float4*)(bb)     = *(const float4*)&Bs[kk][tx * 4];
            *(float4*)(bb + 4) = *(const float4*)&Bs[kk][64 + tx * 4];
            #pragma unroll
            for (int i = 0; i < 8; ++i)
                #pragma unroll
                for (int j = 0; j < 8; ++j)
                    acc[i][j] = fmaf(a[i], bb[j], acc[i][j]);
        }
        __syncthreads();
    }

    #pragma unroll
    for (int i = 0; i < 8; ++i) {
        int gm = by * 128 + ((i < 4) ? (ty * 4 + i) : (64 + ty * 4 + i - 4));
        #pragma unroll
        for (int j = 0; j < 8; ++j) {
            int gn = bx * 128 + ((j < 4) ? (tx * 4 + j) : (64 + tx * 4 + j - 4));
            float val = acc[i][j] + bias[gn];
            if (layout == 0) {
                C[(size_t)gm * N + gn] = val;
            } else {
                int bb_ = gm >> 11, ss = gm & (S - 1);
                int hh = gn >> 6, dd = gn & 63;
                C[(((size_t)(bb_ * H + hh)) * S + ss) * HD + dd] = val;
            }
        }
    }
}

// ---------------- fused flash attention ----------------
// grid (S/64, B*H), 256 threads, tiles BM=BN=64, HD=64
__global__ void __launch_bounds__(256) k_flash(const float* __restrict__ mod)
{
    extern __shared__ float sh[];
    float* Qs = sh;               // 64 x 64
    float* Ks = sh + 64 * 64;     // 64 x 68 (padded)
    float* Vs = Ks + 64 * 68;     // 64 x 64
    float* Ps = Vs + 64 * 64;     // 64 x 68 (padded)

    const int t = threadIdx.x;
    const int tx = t & 15, ty = t >> 4;
    const int qt = blockIdx.x;
    const int bh = blockIdx.y;
    const int b = bh >> 4, h = bh & 15;

    const float* qb = g_q + ((size_t)bh * S + qt * 64) * HD;
    const float* kb = g_k + (size_t)bh * S * HD;
    const float* vb = g_v + (size_t)bh * S * HD;
    const float* mb = mod + (size_t)b * S * S + (size_t)(qt * 64) * S;

    const int lr = t >> 4;        // 0..15
    const int lc = (t & 15) * 4;  // 0..60

    #pragma unroll
    for (int it = 0; it < 4; ++it) {
        int r = lr + it * 16;
        *(float4*)&Qs[r * 64 + lc] = *(const float4*)(qb + r * 64 + lc);
    }

    bool qm[4];
    #pragma unroll
    for (int i = 0; i < 4; ++i)
        qm[i] = g_qmask[b * S + qt * 64 + i * 16 + ty] != 0;

    float m_i[4], l_i[4], o[4][4];
    #pragma unroll
    for (int i = 0; i < 4; ++i) {
        m_i[i] = -1e30f;
        l_i[i] = 0.f;
        #pragma unroll
        for (int j = 0; j < 4; ++j) o[i][j] = 0.f;
    }

    for (int nt = 0; nt < S / 64; ++nt) {
        #pragma unroll
        for (int it = 0; it < 4; ++it) {
            int r = lr + it * 16;
            *(float4*)&Ks[r * 68 + lc] =
                *(const float4*)(kb + (size_t)(nt * 64 + r) * HD + lc);
            *(float4*)&Vs[r * 64 + lc] =
                *(const float4*)(vb + (size_t)(nt * 64 + r) * HD + lc);
        }
        __syncthreads();

        // S = Q @ K^T (per-thread 4x4 over (query, key))
        float s[4][4];
        #pragma unroll
        for (int i = 0; i < 4; ++i)
            #pragma unroll
            for (int j = 0; j < 4; ++j) s[i][j] = 0.f;

        #pragma unroll
        for (int kk = 0; kk < 64; kk += 4) {
            float4 a4[4], b4[4];
            #pragma unroll
            for (int i = 0; i < 4; ++i)
                a4[i] = *(const float4*)&Qs[(i * 16 + ty) * 64 + kk];
            #pragma unroll
            for (int j = 0; j < 4; ++j)
                b4[j] = *(const float4*)&Ks[(j * 16 + tx) * 68 + kk];
            #pragma unroll
            for (int i = 0; i < 4; ++i)
                #pragma unroll
                for (int j = 0; j < 4; ++j) {
                    s[i][j] = fmaf(a4[i].x, b4[j].x, s[i][j]);
                    s[i][j] = fmaf(a4[i].y, b4[j].y, s[i][j]);
                    s[i][j] = fmaf(a4[i].z, b4[j].z, s[i][j]);
                    s[i][j] = fmaf(a4[i].w, b4[j].w, s[i][j]);
                }
        }

        // modifier * scale, query-axis padding mask, online softmax
        #pragma unroll
        for (int i = 0; i < 4; ++i) {
            int qrow = i * 16 + ty;
            const float* mrow = mb + (size_t)qrow * S + nt * 64;
            float sv[4];
            #pragma unroll
            for (int j = 0; j < 4; ++j) {
                float e = s[i][j] * 0.125f * mrow[j * 16 + tx];
                sv[j] = qm[i] ? -1e10f : e;
            }
            float mx = fmaxf(fmaxf(sv[0], sv[1]), fmaxf(sv[2], sv[3]));
            #pragma unroll
            for (int w = 1; w < 16; w <<= 1)
                mx = fmaxf(mx, __shfl_xor_sync(0xffffffffu, mx, w));
            float mn = fmaxf(m_i[i], mx);
            float corr = __expf(m_i[i] - mn);
            float rs = 0.f;
            #pragma unroll
            for (int j = 0; j < 4; ++j) {
                float p = __expf(sv[j] - mn);
                Ps[qrow * 68 + j * 16 + tx] = p;
                rs += p;
            }
            #pragma unroll
            for (int w = 1; w < 16; w <<= 1)
                rs += __shfl_xor_sync(0xffffffffu, rs, w);
            l_i[i] = l_i[i] * corr + rs;
            m_i[i] = mn;
            #pragma unroll
            for (int j = 0; j < 4; ++j) o[i][j] *= corr;
        }
        __syncthreads();

        // O += P @ V (per-thread 4x4 over (query, dim))
        #pragma unroll
        for (int kk = 0; kk < 64; kk += 4) {
            float a4[4][4];
            #pragma unroll
            for (int i = 0; i < 4; ++i) {
                float4 tmp = *(const float4*)&Ps[(i * 16 + ty) * 68 + kk];
                a4[i][0] = tmp.x; a4[i][1] = tmp.y;
                a4[i][2] = tmp.z; a4[i][3] = tmp.w;
            }
            #pragma unroll
            for (int c = 0; c < 4; ++c) {
                float bb[4];
                #pragma unroll
                for (int j = 0; j < 4; ++j)
                    bb[j] = Vs[(kk + c) * 64 + j * 16 + tx];
                #pragma unroll
                for (int i = 0; i < 4; ++i)
                    #pragma unroll
                    for (int j = 0; j < 4; ++j)
                        o[i][j] = fmaf(a4[i][c], bb[j], o[i][j]);
            }
        }
        __syncthreads();
    }

    // normalize and write [B,S,D] so the output projection reads row-major
    #pragma unroll
    for (int i = 0; i < 4; ++i) {
        float inv = 1.0f / l_i[i];
        int qg = qt * 64 + i * 16 + ty;
        #pragma unroll
        for (int j = 0; j < 4; ++j) {
            int d = j * 16 + tx;
            g_att[((size_t)b * S + qg) * D + h * HD + d] = o[i][j] * inv;
        }
    }
}

// ---------------- launch ----------------
extern "C" void kernel_launch(void* const* d_in, const int* in_sizes, int n_in,
                              void* d_out, int out_size)
{
    const float* x   = (const float*)d_in[0];
    const void*  kpm = d_in[1];
    const float* mod = (const float*)d_in[2];
    const float* Wq  = (const float*)d_in[3];
    const float* bq  = (const float*)d_in[4];
    const float* Wk  = (const float*)d_in[5];
    const float* bk  = (const float*)d_in[6];
    const float* Wv  = (const float*)d_in[7];
    const float* bv  = (const float*)d_in[8];
    const float* Wo  = (const float*)d_in[9];
    const float* bo  = (const float*)d_in[10];
    float* out = (float*)d_out;

    float *qp, *kp, *vp, *ap;
    cudaGetSymbolAddress((void**)&qp, g_q);
    cudaGetSymbolAddress((void**)&kp, g_k);
    cudaGetSymbolAddress((void**)&vp, g_v);
    cudaGetSymbolAddress((void**)&ap, g_att);

    k_init_sig<<<1, 1>>>();
    k_detect<<<(B * S + 255) / 256, 256>>>((const unsigned char*)kpm);
    k_convert<<<(B * S + 255) / 256, 256>>>(kpm);

    dim3 gg(D / 128, M / 128);
    k_gemm<<<gg, 256>>>(x, Wq, bq, qp, 1);
    k_gemm<<<gg, 256>>>(x, Wk, bk, kp, 1);
    k_gemm<<<gg, 256>>>(x, Wv, bv, vp, 1);

    constexpr int SMEM = (64 * 64 + 64 * 68 + 64 * 64 + 64 * 68) * 4;  // 67584 B
    cudaFuncSetAttribute(k_flash, cudaFuncAttributeMaxDynamicSharedMemorySize, SMEM);
    k_flash<<<dim3(S / 64, B * H), 256, SMEM>>>(mod);

    k_gemm<<<gg, 256>>>(ap, Wo, bo, out, 0);
}

// round 3
// speedup vs baseline: 2.5002x; 2.5002x over previous
#include <cuda_runtime.h>
#include <cstdint>

static constexpr int B = 4, S = 2048, D = 1024, H = 16, HD = 64;
static constexpr int M = B * S;  // 8192

// Scratch (allocation-free: __device__ globals)
__device__ float g_q[(size_t)B * H * S * HD];
__device__ float g_k[(size_t)B * H * S * HD];
__device__ float g_v[(size_t)B * H * S * HD];
__device__ float g_att[(size_t)B * S * D];
__device__ unsigned char g_qmask[B * S];
__device__ int g_sig;

// ---------------- tf32 helpers ----------------
__device__ __forceinline__ unsigned f2tf(float x) {
    unsigned u;
    asm("cvt.rna.tf32.f32 %0, %1;" : "=r"(u) : "f"(x));
    return u;
}
__device__ __forceinline__ float f2tff(float x) { return __uint_as_float(f2tf(x)); }

__device__ __forceinline__ void mma_tf32(float& c0, float& c1, float& c2, float& c3,
                                         unsigned a0, unsigned a1, unsigned a2, unsigned a3,
                                         unsigned b0, unsigned b1) {
    asm("mma.sync.aligned.m16n8k8.row.col.f32.tf32.tf32.f32 "
        "{%0,%1,%2,%3}, {%4,%5,%6,%7}, {%8,%9}, {%0,%1,%2,%3};"
        : "+f"(c0), "+f"(c1), "+f"(c2), "+f"(c3)
        : "r"(a0), "r"(a1), "r"(a2), "r"(a3), "r"(b0), "r"(b1));
}

// ---------------- mask dtype canonicalization ----------------
__global__ void k_init_sig() { g_sig = 0; }

__global__ void k_detect(const unsigned char* __restrict__ p) {
    int q = blockIdx.x * blockDim.x + threadIdx.x;
    if (q < B * S) {
        if (p[q] != 0) atomicOr(&g_sig, 1 << (q & 3));
    }
}

__global__ void k_convert(const void* __restrict__ p) {
    int q = blockIdx.x * blockDim.x + threadIdx.x;
    if (q >= B * S) return;
    int sig = g_sig;
    bool m;
    if (sig & 0x2)      m = ((const unsigned char*)p)[q] != 0;
    else if (sig & 0x4) m = ((const float*)p)[q] != 0.0f;
    else                m = ((const int*)p)[q] != 0;
    g_qmask[q] = m ? 1 : 0;
}

// ---------------- tf32 tensor-core SGEMM ----------------
// C[M,1024] = A[M,1024] @ W[1024,1024] + bias
// layout 0: row-major [M,N];  layout 1: scatter to [B,H,S,HD]
__global__ void __launch_bounds__(256) k_gemm(const float* __restrict__ A,
                                              const float* __restrict__ W,
                                              const float* __restrict__ bias,
                                              float* __restrict__ C,
                                              int layout)
{
    constexpr int N = 1024, K = 1024;
    __shared__ float As[128][20];   // [m][k], pad 20 -> conflict-free A frags
    __shared__ float Bs[16][136];   // [k][n], pad 136 -> conflict-free B frags

    const int t = threadIdx.x, lane = t & 31, wid = t >> 5;
    const int g = lane >> 2, q = lane & 3;
    const int wm = (wid & 3) * 32;     // warp rows
    const int wn = (wid >> 2) * 64;    // warp cols
    const int bx = blockIdx.x, by = blockIdx.y;

    float c[2][8][4];
    #pragma unroll
    for (int mf = 0; mf < 2; ++mf)
        #pragma unroll
        for (int nf = 0; nf < 8; ++nf)
            #pragma unroll
            for (int i = 0; i < 4; ++i) c[mf][nf][i] = 0.f;

    // A tile: 128x16 = 512 float4; B tile: 16x128 = 512 float4. 2 each per thread.
    const int aRow0 = t >> 2,        aK0 = (t & 3) * 4;
    const int aRow1 = (t + 256) >> 2, aK1 = aK0;
    const int bK0 = t >> 5,          bC0 = (t & 31) * 4;
    const int bK1 = (t + 256) >> 5,  bC1 = bC0;

    const float* Abase = A + (size_t)(by * 128) * K;
    const float* Wbase = W + bx * 128;

    float4 pa0 = *(const float4*)(Abase + (size_t)aRow0 * K + aK0);
    float4 pa1 = *(const float4*)(Abase + (size_t)aRow1 * K + aK1);
    float4 pb0 = *(const float4*)(Wbase + (size_t)bK0 * N + bC0);
    float4 pb1 = *(const float4*)(Wbase + (size_t)bK1 * N + bC1);

    for (int kb = 0; kb < K; kb += 16) {
        float4 v;
        v.x = f2tff(pa0.x); v.y = f2tff(pa0.y); v.z = f2tff(pa0.z); v.w = f2tff(pa0.w);
        *(float4*)&As[aRow0][aK0] = v;
        v.x = f2tff(pa1.x); v.y = f2tff(pa1.y); v.z = f2tff(pa1.z); v.w = f2tff(pa1.w);
        *(float4*)&As[aRow1][aK1] = v;
        v.x = f2tff(pb0.x); v.y = f2tff(pb0.y); v.z = f2tff(pb0.z); v.w = f2tff(pb0.w);
        *(float4*)&Bs[bK0][bC0] = v;
        v.x = f2tff(pb1.x); v.y = f2tff(pb1.y); v.z = f2tff(pb1.z); v.w = f2tff(pb1.w);
        *(float4*)&Bs[bK1][bC1] = v;
        __syncthreads();

        if (kb + 16 < K) {
            pa0 = *(const float4*)(Abase + (size_t)aRow0 * K + kb + 16 + aK0);
            pa1 = *(const float4*)(Abase + (size_t)aRow1 * K + kb + 16 + aK1);
            pb0 = *(const float4*)(Wbase + (size_t)(kb + 16 + bK0) * N + bC0);
            pb1 = *(const float4*)(Wbase + (size_t)(kb + 16 + bK1) * N + bC1);
        }

        #pragma unroll
        for (int ks = 0; ks < 2; ++ks) {
            const int k0 = ks * 8;
            unsigned a[2][4];
            #pragma unroll
            for (int mf = 0; mf < 2; ++mf) {
                int r = wm + mf * 16 + g;
                a[mf][0] = __float_as_uint(As[r][k0 + q]);
                a[mf][1] = __float_as_uint(As[r + 8][k0 + q]);
                a[mf][2] = __float_as_uint(As[r][k0 + q + 4]);
                a[mf][3] = __float_as_uint(As[r + 8][k0 + q + 4]);
            }
            #pragma unroll
            for (int nf = 0; nf < 8; ++nf) {
                int col = wn + nf * 8 + g;
                unsigned b0 = __float_as_uint(Bs[k0 + q][col]);
                unsigned b1 = __float_as_uint(Bs[k0 + q + 4][col]);
                #pragma unroll
                for (int mf = 0; mf < 2; ++mf)
                    mma_tf32(c[mf][nf][0], c[mf][nf][1], c[mf][nf][2], c[mf][nf][3],
                             a[mf][0], a[mf][1], a[mf][2], a[mf][3], b0, b1);
            }
        }
        __syncthreads();
    }

    // epilogue: bias + store
    #pragma unroll
    for (int mf = 0; mf < 2; ++mf) {
        #pragma unroll
        for (int half = 0; half < 2; ++half) {
            int gm = by * 128 + wm + mf * 16 + g + half * 8;
            #pragma unroll
            for (int nf = 0; nf < 8; ++nf) {
                int gn = bx * 128 + wn + nf * 8 + 2 * q;
                float v0 = c[mf][nf][half * 2 + 0] + bias[gn];
                float v1 = c[mf][nf][half * 2 + 1] + bias[gn + 1];
                float2 fv = make_float2(v0, v1);
                if (layout == 0) {
                    *(float2*)&C[(size_t)gm * N + gn] = fv;
                } else {
                    int bb_ = gm >> 11, ss = gm & (S - 1);
                    int hh = gn >> 6, dd = gn & 63;
                    *(float2*)&C[(((size_t)(bb_ * H + hh)) * S + ss) * HD + dd] = fv;
                }
            }
        }
    }
}

// ---------------- fused flash attention (tf32 mma) ----------------
// grid (B*H, S/64), 128 threads (4 warps); warp w owns query rows [16w,16w+16)
__global__ void __launch_bounds__(128) k_flash(const float* __restrict__ mod)
{
    extern __shared__ float sh[];
    float* Qs = sh;                 // [64][68] tf32
    float* Ks = Qs + 64 * 68;       // [64][68] tf32
    float* Vs = Ks + 64 * 68;       // [64][72] tf32
    float* Ps = Vs + 64 * 72;       // [64][68] tf32

    const int t = threadIdx.x, lane = t & 31, w = t >> 5;
    const int g = lane >> 2, q = lane & 3;
    const int bh = blockIdx.x, qt = blockIdx.y;
    const int b = bh >> 4, h = bh & 15;

    const float* qg = g_q + ((size_t)bh * S + qt * 64) * HD;
    const float* kg = g_k + (size_t)bh * S * HD;
    const float* vg = g_v + (size_t)bh * S * HD;

    // load Q tile (convert to tf32)
    #pragma unroll
    for (int i = 0; i < 8; ++i) {
        int idx = t + i * 128;
        int r = idx >> 4, cc = (idx & 15) * 4;
        float4 v = *(const float4*)(qg + r * 64 + cc);
        float4 cv;
        cv.x = f2tff(v.x); cv.y = f2tff(v.y); cv.z = f2tff(v.z); cv.w = f2tff(v.w);
        *(float4*)&Qs[r * 68 + cc] = cv;
    }

    const int r0 = w * 16 + g;
    const bool qm0 = g_qmask[b * S + qt * 64 + r0] != 0;
    const bool qm1 = g_qmask[b * S + qt * 64 + r0 + 8] != 0;
    const float* m0p = mod + ((size_t)b * S + qt * 64 + r0) * S;
    const float* m1p = m0p + (size_t)8 * S;

    float o[8][4];
    #pragma unroll
    for (int nf = 0; nf < 8; ++nf)
        #pragma unroll
        for (int i = 0; i < 4; ++i) o[nf][i] = 0.f;
    float mr0 = -1e30f, mr1 = -1e30f, l0 = 0.f, l1 = 0.f;

    __syncthreads();

    for (int nt = 0; nt < S / 64; ++nt) {
        if (nt) __syncthreads();
        #pragma unroll
        for (int i = 0; i < 8; ++i) {
            int idx = t + i * 128;
            int r = idx >> 4, cc = (idx & 15) * 4;
            float4 kv = *(const float4*)(kg + (size_t)(nt * 64 + r) * 64 + cc);
            float4 vv = *(const float4*)(vg + (size_t)(nt * 64 + r) * 64 + cc);
            float4 c1, c2;
            c1.x = f2tff(kv.x); c1.y = f2tff(kv.y); c1.z = f2tff(kv.z); c1.w = f2tff(kv.w);
            c2.x = f2tff(vv.x); c2.y = f2tff(vv.y); c2.z = f2tff(vv.z); c2.w = f2tff(vv.w);
            *(float4*)&Ks[r * 68 + cc] = c1;
            *(float4*)&Vs[r * 72 + cc] = c2;
        }
        __syncthreads();

        // S = Q @ K^T
        float s[8][4];
        #pragma unroll
        for (int nf = 0; nf < 8; ++nf)
            #pragma unroll
            for (int i = 0; i < 4; ++i) s[nf][i] = 0.f;

        #pragma unroll
        for (int kk = 0; kk < 8; ++kk) {
            const int k0 = kk * 8;
            unsigned a0 = __float_as_uint(Qs[r0 * 68 + k0 + q]);
            unsigned a1 = __float_as_uint(Qs[(r0 + 8) * 68 + k0 + q]);
            unsigned a2 = __float_as_uint(Qs[r0 * 68 + k0 + q + 4]);
            unsigned a3 = __float_as_uint(Qs[(r0 + 8) * 68 + k0 + q + 4]);
            #pragma unroll
            for (int nf = 0; nf < 8; ++nf) {
                unsigned b0 = __float_as_uint(Ks[(nf * 8 + g) * 68 + k0 + q]);
                unsigned b1 = __float_as_uint(Ks[(nf * 8 + g) * 68 + k0 + q + 4]);
                mma_tf32(s[nf][0], s[nf][1], s[nf][2], s[nf][3], a0, a1, a2, a3, b0, b1);
            }
        }

        // modifier * scale, query-axis mask, online softmax
        float mx0 = -1e30f, mx1 = -1e30f;
        #pragma unroll
        for (int nf = 0; nf < 8; ++nf) {
            float2 md0 = *(const float2*)(m0p + nt * 64 + nf * 8 + 2 * q);
            float2 md1 = *(const float2*)(m1p + nt * 64 + nf * 8 + 2 * q);
            s[nf][0] = qm0 ? -1e10f : s[nf][0] * 0.125f * md0.x;
            s[nf][1] = qm0 ? -1e10f : s[nf][1] * 0.125f * md0.y;
            s[nf][2] = qm1 ? -1e10f : s[nf][2] * 0.125f * md1.x;
            s[nf][3] = qm1 ? -1e10f : s[nf][3] * 0.125f * md1.y;
            mx0 = fmaxf(mx0, fmaxf(s[nf][0], s[nf][1]));
            mx1 = fmaxf(mx1, fmaxf(s[nf][2], s[nf][3]));
        }
        mx0 = fmaxf(mx0, __shfl_xor_sync(0xffffffffu, mx0, 1));
        mx0 = fmaxf(mx0, __shfl_xor_sync(0xffffffffu, mx0, 2));
        mx1 = fmaxf(mx1, __shfl_xor_sync(0xffffffffu, mx1, 1));
        mx1 = fmaxf(mx1, __shfl_xor_sync(0xffffffffu, mx1, 2));

        float mn0 = fmaxf(mr0, mx0), mn1 = fmaxf(mr1, mx1);
        float co0 = __expf(mr0 - mn0), co1 = __expf(mr1 - mn1);
        float rs0 = 0.f, rs1 = 0.f;
        #pragma unroll
        for (int nf = 0; nf < 8; ++nf) {
            float p0 = __expf(s[nf][0] - mn0);
            float p1 = __expf(s[nf][1] - mn0);
            float p2 = __expf(s[nf][2] - mn1);
            float p3 = __expf(s[nf][3] - mn1);
            rs0 += p0 + p1; rs1 += p2 + p3;
            *(float2*)&Ps[r0 * 68 + nf * 8 + 2 * q]       = make_float2(f2tff(p0), f2tff(p1));
            *(float2*)&Ps[(r0 + 8) * 68 + nf * 8 + 2 * q] = make_float2(f2tff(p2), f2tff(p3));
        }
        rs0 += __shfl_xor_sync(0xffffffffu, rs0, 1);
        rs0 += __shfl_xor_sync(0xffffffffu, rs0, 2);
        rs1 += __shfl_xor_sync(0xffffffffu, rs1, 1);
        rs1 += __shfl_xor_sync(0xffffffffu, rs1, 2);
        l0 = l0 * co0 + rs0;
        l1 = l1 * co1 + rs1;
        mr0 = mn0; mr1 = mn1;
        #pragma unroll
        for (int nf = 0; nf < 8; ++nf) {
            o[nf][0] *= co0; o[nf][1] *= co0;
            o[nf][2] *= co1; o[nf][3] *= co1;
        }
        __syncthreads();

        // O += P @ V
        #pragma unroll
        for (int kk = 0; kk < 8; ++kk) {
            const int k0 = kk * 8;
            unsigned a0 = __float_as_uint(Ps[r0 * 68 + k0 + q]);
            unsigned a1 = __float_as_uint(Ps[(r0 + 8) * 68 + k0 + q]);
            unsigned a2 = __float_as_uint(Ps[r0 * 68 + k0 + q + 4]);
            unsigned a3 = __float_as_uint(Ps[(r0 + 8) * 68 + k0 + q + 4]);
            #pragma unroll
            for (int nf = 0; nf < 8; ++nf) {
                unsigned b0 = __float_as_uint(Vs[(k0 + q) * 72 + nf * 8 + g]);
                unsigned b1 = __float_as_uint(Vs[(k0 + q + 4) * 72 + nf * 8 + g]);
                mma_tf32(o[nf][0], o[nf][1], o[nf][2], o[nf][3], a0, a1, a2, a3, b0, b1);
            }
        }
    }

    // normalize, write [B,S,D]
    float i0 = 1.0f / l0, i1 = 1.0f / l1;
    float* ob = g_att + ((size_t)b * S + qt * 64) * D + h * 64;
    #pragma unroll
    for (int nf = 0; nf < 8; ++nf) {
        *(float2*)&ob[(size_t)r0 * D + nf * 8 + 2 * q] =
            make_float2(o[nf][0] * i0, o[nf][1] * i0);
        *(float2*)&ob[(size_t)(r0 + 8) * D + nf * 8 + 2 * q] =
            make_float2(o[nf][2] * i1, o[nf][3] * i1);
    }
}

// ---------------- launch ----------------
extern "C" void kernel_launch(void* const* d_in, const int* in_sizes, int n_in,
                              void* d_out, int out_size)
{
    const float* x   = (const float*)d_in[0];
    const void*  kpm = d_in[1];
    const float* mod = (const float*)d_in[2];
    const float* Wq  = (const float*)d_in[3];
    const float* bq  = (const float*)d_in[4];
    const float* Wk  = (const float*)d_in[5];
    const float* bk  = (const float*)d_in[6];
    const float* Wv  = (const float*)d_in[7];
    const float* bv  = (const float*)d_in[8];
    const float* Wo  = (const float*)d_in[9];
    const float* bo  = (const float*)d_in[10];
    float* out = (float*)d_out;

    float *qp, *kp, *vp, *ap;
    cudaGetSymbolAddress((void**)&qp, g_q);
    cudaGetSymbolAddress((void**)&kp, g_k);
    cudaGetSymbolAddress((void**)&vp, g_v);
    cudaGetSymbolAddress((void**)&ap, g_att);

    k_init_sig<<<1, 1>>>();
    k_detect<<<(B * S + 255) / 256, 256>>>((const unsigned char*)kpm);
    k_convert<<<(B * S + 255) / 256, 256>>>(kpm);

    dim3 gg(D / 128, M / 128);
    k_gemm<<<gg, 256>>>(x, Wq, bq, qp, 1);
    k_gemm<<<gg, 256>>>(x, Wk, bk, kp, 1);
    k_gemm<<<gg, 256>>>(x, Wv, bv, vp, 1);

    constexpr int SMEM = (64 * 68 + 64 * 68 + 64 * 72 + 64 * 68) * 4;  // 70656 B
    cudaFuncSetAttribute(k_flash, cudaFuncAttributeMaxDynamicSharedMemorySize, SMEM);
    k_flash<<<dim3(B * H, S / 64), 128, SMEM>>>(mod);

    k_gemm<<<gg, 256>>>(ap, Wo, bo, out, 0);
}

// round 4
// speedup vs baseline: 2.5734x; 1.0293x over previous
#include <cuda_runtime.h>
#include <cstdint>

static constexpr int B = 4, S = 2048, D = 1024, H = 16, HD = 64;
static constexpr int M = B * S;  // 8192

// Scratch (allocation-free: __device__ globals)
__device__ float g_q[(size_t)B * H * S * HD];
__device__ float g_k[(size_t)B * H * S * HD];
__device__ float g_v[(size_t)B * H * S * HD];
__device__ float g_att[(size_t)B * S * D];
__device__ unsigned char g_qmask[B * S];
__device__ int g_sig;

// ---------------- tf32 helpers ----------------
__device__ __forceinline__ unsigned f2tf(float x) {
    unsigned u;
    asm("cvt.rna.tf32.f32 %0, %1;" : "=r"(u) : "f"(x));
    return u;
}
__device__ __forceinline__ float f2tff(float x) { return __uint_as_float(f2tf(x)); }

__device__ __forceinline__ void mma_tf32(float& c0, float& c1, float& c2, float& c3,
                                         unsigned a0, unsigned a1, unsigned a2, unsigned a3,
                                         unsigned b0, unsigned b1) {
    asm("mma.sync.aligned.m16n8k8.row.col.f32.tf32.tf32.f32 "
        "{%0,%1,%2,%3}, {%4,%5,%6,%7}, {%8,%9}, {%0,%1,%2,%3};"
        : "+f"(c0), "+f"(c1), "+f"(c2), "+f"(c3)
        : "r"(a0), "r"(a1), "r"(a2), "r"(a3), "r"(b0), "r"(b1));
}

// ---------------- mask dtype canonicalization ----------------
__global__ void k_init_sig() { g_sig = 0; }

__global__ void k_detect(const unsigned char* __restrict__ p) {
    int q = blockIdx.x * blockDim.x + threadIdx.x;
    if (q < B * S) {
        if (p[q] != 0) atomicOr(&g_sig, 1 << (q & 3));
    }
}

__global__ void k_convert(const void* __restrict__ p) {
    int q = blockIdx.x * blockDim.x + threadIdx.x;
    if (q >= B * S) return;
    int sig = g_sig;
    bool m;
    if (sig & 0x2)      m = ((const unsigned char*)p)[q] != 0;
    else if (sig & 0x4) m = ((const float*)p)[q] != 0.0f;
    else                m = ((const int*)p)[q] != 0;
    g_qmask[q] = m ? 1 : 0;
}

// ---------------- tf32 tensor-core SGEMM (double-buffered) ----------------
// C[M,1024] = A[M,1024] @ W[1024,1024] + bias
// layout 0: row-major [M,N];  layout 1: scatter to [B,H,S,HD]
__global__ void __launch_bounds__(256) k_gemm(const float* __restrict__ A,
                                              const float* __restrict__ W,
                                              const float* __restrict__ bias,
                                              float* __restrict__ C,
                                              int layout)
{
    constexpr int N = 1024, K = 1024;
    __shared__ float As[2][128][20];   // [m][k], pad 20 -> conflict-free A frags
    __shared__ float Bs[2][16][136];   // [k][n], pad 136 -> conflict-free B frags

    const int t = threadIdx.x, lane = t & 31, wid = t >> 5;
    const int g = lane >> 2, q = lane & 3;
    const int wm = (wid & 3) * 32;     // warp rows
    const int wn = (wid >> 2) * 64;    // warp cols
    const int bx = blockIdx.x, by = blockIdx.y;

    float c[2][8][4];
    #pragma unroll
    for (int mf = 0; mf < 2; ++mf)
        #pragma unroll
        for (int nf = 0; nf < 8; ++nf)
            #pragma unroll
            for (int i = 0; i < 4; ++i) c[mf][nf][i] = 0.f;

    const int aRow0 = t >> 2,         aK0 = (t & 3) * 4;
    const int aRow1 = (t + 256) >> 2, aK1 = aK0;
    const int bK0 = t >> 5,           bC0 = (t & 31) * 4;
    const int bK1 = (t + 256) >> 5,   bC1 = bC0;

    const float* Abase = A + (size_t)(by * 128) * K;
    const float* Wbase = W + bx * 128;

    float4 pa0 = *(const float4*)(Abase + (size_t)aRow0 * K + aK0);
    float4 pa1 = *(const float4*)(Abase + (size_t)aRow1 * K + aK1);
    float4 pb0 = *(const float4*)(Wbase + (size_t)bK0 * N + bC0);
    float4 pb1 = *(const float4*)(Wbase + (size_t)bK1 * N + bC1);

    // store tile 0
    {
        float4 v;
        v.x = f2tff(pa0.x); v.y = f2tff(pa0.y); v.z = f2tff(pa0.z); v.w = f2tff(pa0.w);
        *(float4*)&As[0][aRow0][aK0] = v;
        v.x = f2tff(pa1.x); v.y = f2tff(pa1.y); v.z = f2tff(pa1.z); v.w = f2tff(pa1.w);
        *(float4*)&As[0][aRow1][aK1] = v;
        v.x = f2tff(pb0.x); v.y = f2tff(pb0.y); v.z = f2tff(pb0.z); v.w = f2tff(pb0.w);
        *(float4*)&Bs[0][bK0][bC0] = v;
        v.x = f2tff(pb1.x); v.y = f2tff(pb1.y); v.z = f2tff(pb1.z); v.w = f2tff(pb1.w);
        *(float4*)&Bs[0][bK1][bC1] = v;
    }
    __syncthreads();

    constexpr int NT = K / 16;  // 64
    for (int kt = 0; kt < NT; ++kt) {
        const int cur = kt & 1;
        const bool more = (kt + 1 < NT);
        if (more) {
            int kb = (kt + 1) * 16;
            pa0 = *(const float4*)(Abase + (size_t)aRow0 * K + kb + aK0);
            pa1 = *(const float4*)(Abase + (size_t)aRow1 * K + kb + aK1);
            pb0 = *(const float4*)(Wbase + (size_t)(kb + bK0) * N + bC0);
            pb1 = *(const float4*)(Wbase + (size_t)(kb + bK1) * N + bC1);
        }

        #pragma unroll
        for (int ks = 0; ks < 2; ++ks) {
            const int k0 = ks * 8;
            unsigned a[2][4];
            #pragma unroll
            for (int mf = 0; mf < 2; ++mf) {
                int r = wm + mf * 16 + g;
                a[mf][0] = __float_as_uint(As[cur][r][k0 + q]);
                a[mf][1] = __float_as_uint(As[cur][r + 8][k0 + q]);
                a[mf][2] = __float_as_uint(As[cur][r][k0 + q + 4]);
                a[mf][3] = __float_as_uint(As[cur][r + 8][k0 + q + 4]);
            }
            #pragma unroll
            for (int nf = 0; nf < 8; ++nf) {
                int col = wn + nf * 8 + g;
                unsigned b0 = __float_as_uint(Bs[cur][k0 + q][col]);
                unsigned b1 = __float_as_uint(Bs[cur][k0 + q + 4][col]);
                #pragma unroll
                for (int mf = 0; mf < 2; ++mf)
                    mma_tf32(c[mf][nf][0], c[mf][nf][1], c[mf][nf][2], c[mf][nf][3],
                             a[mf][0], a[mf][1], a[mf][2], a[mf][3], b0, b1);
            }
        }

        if (more) {
            const int nxt = cur ^ 1;
            float4 v;
            v.x = f2tff(pa0.x); v.y = f2tff(pa0.y); v.z = f2tff(pa0.z); v.w = f2tff(pa0.w);
            *(float4*)&As[nxt][aRow0][aK0] = v;
            v.x = f2tff(pa1.x); v.y = f2tff(pa1.y); v.z = f2tff(pa1.z); v.w = f2tff(pa1.w);
            *(float4*)&As[nxt][aRow1][aK1] = v;
            v.x = f2tff(pb0.x); v.y = f2tff(pb0.y); v.z = f2tff(pb0.z); v.w = f2tff(pb0.w);
            *(float4*)&Bs[nxt][bK0][bC0] = v;
            v.x = f2tff(pb1.x); v.y = f2tff(pb1.y); v.z = f2tff(pb1.z); v.w = f2tff(pb1.w);
            *(float4*)&Bs[nxt][bK1][bC1] = v;
            __syncthreads();
        }
    }

    // epilogue: bias + store
    #pragma unroll
    for (int mf = 0; mf < 2; ++mf) {
        #pragma unroll
        for (int half = 0; half < 2; ++half) {
            int gm = by * 128 + wm + mf * 16 + g + half * 8;
            #pragma unroll
            for (int nf = 0; nf < 8; ++nf) {
                int gn = bx * 128 + wn + nf * 8 + 2 * q;
                float v0 = c[mf][nf][half * 2 + 0] + bias[gn];
                float v1 = c[mf][nf][half * 2 + 1] + bias[gn + 1];
                float2 fv = make_float2(v0, v1);
                if (layout == 0) {
                    *(float2*)&C[(size_t)gm * N + gn] = fv;
                } else {
                    int bb_ = gm >> 11, ss = gm & (S - 1);
                    int hh = gn >> 6, dd = gn & 63;
                    *(float2*)&C[(((size_t)(bb_ * H + hh)) * S + ss) * HD + dd] = fv;
                }
            }
        }
    }
}

// ---------------- fused flash attention (tf32 mma, BM=128) ----------------
// grid (H, B*(S/128)), 256 threads (8 warps); warp w owns query rows [16w,16w+16)
__global__ void __launch_bounds__(256, 2) k_flash(const float* __restrict__ mod)
{
    extern __shared__ float sh[];
    float* Qs = sh;                 // [128][68] tf32
    float* Ks = Qs + 128 * 68;      // [64][68] tf32
    float* Vs = Ks + 64 * 68;       // [64][72] tf32
    float* Ps = Vs + 64 * 72;       // [128][68] tf32

    const int t = threadIdx.x, lane = t & 31, w = t >> 5;
    const int g = lane >> 2, q = lane & 3;
    const int h = blockIdx.x;
    const int by = blockIdx.y;
    const int b = by >> 4, qt = by & 15;   // S/128 = 16 tiles
    const int bh = b * H + h;

    const float* qg = g_q + ((size_t)bh * S + qt * 128) * HD;
    const float* kg = g_k + (size_t)bh * S * HD;
    const float* vg = g_v + (size_t)bh * S * HD;

    // load Q tile (convert to tf32): 128x64 -> 2048 float4
    #pragma unroll
    for (int i = 0; i < 8; ++i) {
        int idx = t + i * 256;
        int r = idx >> 4, cc = (idx & 15) * 4;
        float4 v = *(const float4*)(qg + r * 64 + cc);
        float4 cv;
        cv.x = f2tff(v.x); cv.y = f2tff(v.y); cv.z = f2tff(v.z); cv.w = f2tff(v.w);
        *(float4*)&Qs[r * 68 + cc] = cv;
    }

    const int r0 = w * 16 + g;
    const bool qm0 = g_qmask[b * S + qt * 128 + r0] != 0;
    const bool qm1 = g_qmask[b * S + qt * 128 + r0 + 8] != 0;
    const float* m0p = mod + ((size_t)b * S + qt * 128 + r0) * S;
    const float* m1p = m0p + (size_t)8 * S;

    float o[8][4];
    #pragma unroll
    for (int nf = 0; nf < 8; ++nf)
        #pragma unroll
        for (int i = 0; i < 4; ++i) o[nf][i] = 0.f;
    float mr0 = -1e30f, mr1 = -1e30f, l0 = 0.f, l1 = 0.f;

    __syncthreads();

    for (int nt = 0; nt < S / 64; ++nt) {
        if (nt) __syncthreads();
        // fill K,V tiles: 64x64 each -> 1024 float4 each
        #pragma unroll
        for (int i = 0; i < 4; ++i) {
            int idx = t + i * 256;
            int r = idx >> 4, cc = (idx & 15) * 4;
            float4 kv = *(const float4*)(kg + (size_t)(nt * 64 + r) * 64 + cc);
            float4 vv = *(const float4*)(vg + (size_t)(nt * 64 + r) * 64 + cc);
            float4 c1, c2;
            c1.x = f2tff(kv.x); c1.y = f2tff(kv.y); c1.z = f2tff(kv.z); c1.w = f2tff(kv.w);
            c2.x = f2tff(vv.x); c2.y = f2tff(vv.y); c2.z = f2tff(vv.z); c2.w = f2tff(vv.w);
            *(float4*)&Ks[r * 68 + cc] = c1;
            *(float4*)&Vs[r * 72 + cc] = c2;
        }
        __syncthreads();

        // S = Q @ K^T
        float s[8][4];
        #pragma unroll
        for (int nf = 0; nf < 8; ++nf)
            #pragma unroll
            for (int i = 0; i < 4; ++i) s[nf][i] = 0.f;

        #pragma unroll
        for (int kk = 0; kk < 8; ++kk) {
            const int k0 = kk * 8;
            unsigned a0 = __float_as_uint(Qs[r0 * 68 + k0 + q]);
            unsigned a1 = __float_as_uint(Qs[(r0 + 8) * 68 + k0 + q]);
            unsigned a2 = __float_as_uint(Qs[r0 * 68 + k0 + q + 4]);
            unsigned a3 = __float_as_uint(Qs[(r0 + 8) * 68 + k0 + q + 4]);
            #pragma unroll
            for (int nf = 0; nf < 8; ++nf) {
                unsigned b0 = __float_as_uint(Ks[(nf * 8 + g) * 68 + k0 + q]);
                unsigned b1 = __float_as_uint(Ks[(nf * 8 + g) * 68 + k0 + q + 4]);
                mma_tf32(s[nf][0], s[nf][1], s[nf][2], s[nf][3], a0, a1, a2, a3, b0, b1);
            }
        }

        // modifier * scale, query-axis mask, online softmax
        float mx0 = -1e30f, mx1 = -1e30f;
        #pragma unroll
        for (int nf = 0; nf < 8; ++nf) {
            float2 md0 = *(const float2*)(m0p + nt * 64 + nf * 8 + 2 * q);
            float2 md1 = *(const float2*)(m1p + nt * 64 + nf * 8 + 2 * q);
            s[nf][0] = qm0 ? -1e10f : s[nf][0] * 0.125f * md0.x;
            s[nf][1] = qm0 ? -1e10f : s[nf][1] * 0.125f * md0.y;
            s[nf][2] = qm1 ? -1e10f : s[nf][2] * 0.125f * md1.x;
            s[nf][3] = qm1 ? -1e10f : s[nf][3] * 0.125f * md1.y;
            mx0 = fmaxf(mx0, fmaxf(s[nf][0], s[nf][1]));
            mx1 = fmaxf(mx1, fmaxf(s[nf][2], s[nf][3]));
        }
        mx0 = fmaxf(mx0, __shfl_xor_sync(0xffffffffu, mx0, 1));
        mx0 = fmaxf(mx0, __shfl_xor_sync(0xffffffffu, mx0, 2));
        mx1 = fmaxf(mx1, __shfl_xor_sync(0xffffffffu, mx1, 1));
        mx1 = fmaxf(mx1, __shfl_xor_sync(0xffffffffu, mx1, 2));

        float mn0 = fmaxf(mr0, mx0), mn1 = fmaxf(mr1, mx1);
        float co0 = __expf(mr0 - mn0), co1 = __expf(mr1 - mn1);
        float rs0 = 0.f, rs1 = 0.f;
        #pragma unroll
        for (int nf = 0; nf < 8; ++nf) {
            float p0 = __expf(s[nf][0] - mn0);
            float p1 = __expf(s[nf][1] - mn0);
            float p2 = __expf(s[nf][2] - mn1);
            float p3 = __expf(s[nf][3] - mn1);
            rs0 += p0 + p1; rs1 += p2 + p3;
            *(float2*)&Ps[r0 * 68 + nf * 8 + 2 * q]       = make_float2(f2tff(p0), f2tff(p1));
            *(float2*)&Ps[(r0 + 8) * 68 + nf * 8 + 2 * q] = make_float2(f2tff(p2), f2tff(p3));
        }
        rs0 += __shfl_xor_sync(0xffffffffu, rs0, 1);
        rs0 += __shfl_xor_sync(0xffffffffu, rs0, 2);
        rs1 += __shfl_xor_sync(0xffffffffu, rs1, 1);
        rs1 += __shfl_xor_sync(0xffffffffu, rs1, 2);
        l0 = l0 * co0 + rs0;
        l1 = l1 * co1 + rs1;
        mr0 = mn0; mr1 = mn1;
        #pragma unroll
        for (int nf = 0; nf < 8; ++nf) {
            o[nf][0] *= co0; o[nf][1] *= co0;
            o[nf][2] *= co1; o[nf][3] *= co1;
        }
        __syncwarp();

        // O += P @ V   (Ps rows of this warp written only by this warp)
        #pragma unroll
        for (int kk = 0; kk < 8; ++kk) {
            const int k0 = kk * 8;
            unsigned a0 = __float_as_uint(Ps[r0 * 68 + k0 + q]);
            unsigned a1 = __float_as_uint(Ps[(r0 + 8) * 68 + k0 + q]);
            unsigned a2 = __float_as_uint(Ps[r0 * 68 + k0 + q + 4]);
            unsigned a3 = __float_as_uint(Ps[(r0 + 8) * 68 + k0 + q + 4]);
            #pragma unroll
            for (int nf = 0; nf < 8; ++nf) {
                unsigned b0 = __float_as_uint(Vs[(k0 + q) * 72 + nf * 8 + g]);
                unsigned b1 = __float_as_uint(Vs[(k0 + q + 4) * 72 + nf * 8 + g]);
                mma_tf32(o[nf][0], o[nf][1], o[nf][2], o[nf][3], a0, a1, a2, a3, b0, b1);
            }
        }
    }

    // normalize, write [B,S,D]
    float i0 = 1.0f / l0, i1 = 1.0f / l1;
    float* ob = g_att + ((size_t)b * S + qt * 128) * D + h * 64;
    #pragma unroll
    for (int nf = 0; nf < 8; ++nf) {
        *(float2*)&ob[(size_t)r0 * D + nf * 8 + 2 * q] =
            make_float2(o[nf][0] * i0, o[nf][1] * i0);
        *(float2*)&ob[(size_t)(r0 + 8) * D + nf * 8 + 2 * q] =
            make_float2(o[nf][2] * i1, o[nf][3] * i1);
    }
}

// ---------------- launch ----------------
extern "C" void kernel_launch(void* const* d_in, const int* in_sizes, int n_in,
                              void* d_out, int out_size)
{
    const float* x   = (const float*)d_in[0];
    const void*  kpm = d_in[1];
    const float* mod = (const float*)d_in[2];
    const float* Wq  = (const float*)d_in[3];
    const float* bq  = (const float*)d_in[4];
    const float* Wk  = (const float*)d_in[5];
    const float* bk  = (const float*)d_in[6];
    const float* Wv  = (const float*)d_in[7];
    const float* bv  = (const float*)d_in[8];
    const float* Wo  = (const float*)d_in[9];
    const float* bo  = (const float*)d_in[10];
    float* out = (float*)d_out;

    float *qp, *kp, *vp, *ap;
    cudaGetSymbolAddress((void**)&qp, g_q);
    cudaGetSymbolAddress((void**)&kp, g_k);
    cudaGetSymbolAddress((void**)&vp, g_v);
    cudaGetSymbolAddress((void**)&ap, g_att);

    k_init_sig<<<1, 1>>>();
    k_detect<<<(B * S + 255) / 256, 256>>>((const unsigned char*)kpm);
    k_convert<<<(B * S + 255) / 256, 256>>>(kpm);

    dim3 gg(D / 128, M / 128);
    k_gemm<<<gg, 256>>>(x, Wq, bq, qp, 1);
    k_gemm<<<gg, 256>>>(x, Wk, bk, kp, 1);
    k_gemm<<<gg, 256>>>(x, Wv, bv, vp, 1);

    constexpr int SMEM = (128 * 68 + 64 * 68 + 64 * 72 + 128 * 68) * 4;  // 105472 B
    cudaFuncSetAttribute(k_flash, cudaFuncAttributeMaxDynamicSharedMemorySize, SMEM);
    k_flash<<<dim3(H, B * (S / 128)), 256, SMEM>>>(mod);

    k_gemm<<<gg, 256>>>(ap, Wo, bo, out, 0);
}

// round 5
// speedup vs baseline: 2.5781x; 1.0018x over previous
#include <cuda_runtime.h>
#include <cstdint>

static constexpr int B = 4, S = 2048, D = 1024, H = 16, HD = 64;
static constexpr int M = B * S;  // 8192

// Scratch (allocation-free: __device__ globals)
__device__ float g_q[(size_t)B * H * S * HD];
__device__ float g_k[(size_t)B * H * S * HD];
__device__ float g_v[(size_t)B * H * S * HD];
__device__ float g_att[(size_t)B * S * D];
__device__ unsigned char g_qmask[B * S];
__device__ int g_sig;

// ---------------- tf32 helpers ----------------
__device__ __forceinline__ unsigned f2tf(float x) {
    unsigned u;
    asm("cvt.rna.tf32.f32 %0, %1;" : "=r"(u) : "f"(x));
    return u;
}
__device__ __forceinline__ float f2tff(float x) { return __uint_as_float(f2tf(x)); }

__device__ __forceinline__ void mma_tf32(float& c0, float& c1, float& c2, float& c3,
                                         unsigned a0, unsigned a1, unsigned a2, unsigned a3,
                                         unsigned b0, unsigned b1) {
    asm("mma.sync.aligned.m16n8k8.row.col.f32.tf32.tf32.f32 "
        "{%0,%1,%2,%3}, {%4,%5,%6,%7}, {%8,%9}, {%0,%1,%2,%3};"
        : "+f"(c0), "+f"(c1), "+f"(c2), "+f"(c3)
        : "r"(a0), "r"(a1), "r"(a2), "r"(a3), "r"(b0), "r"(b1));
}

// ---------------- mask dtype canonicalization ----------------
__global__ void k_init_sig() { g_sig = 0; }

__global__ void k_detect(const unsigned char* __restrict__ p) {
    int q = blockIdx.x * blockDim.x + threadIdx.x;
    if (q < B * S) {
        if (p[q] != 0) atomicOr(&g_sig, 1 << (q & 3));
    }
}

__global__ void k_convert(const void* __restrict__ p) {
    int q = blockIdx.x * blockDim.x + threadIdx.x;
    if (q >= B * S) return;
    int sig = g_sig;
    bool m;
    if (sig & 0x2)      m = ((const unsigned char*)p)[q] != 0;
    else if (sig & 0x4) m = ((const float*)p)[q] != 0.0f;
    else                m = ((const int*)p)[q] != 0;
    g_qmask[q] = m ? 1 : 0;
}

// ---------------- tf32 tensor-core SGEMM (double-buffered) ----------------
// C[M,1024] = A[M,1024] @ W[1024,1024] + bias
// layout 0: row-major [M,N];  layout 1: scatter to [B,H,S,HD]
__global__ void __launch_bounds__(256) k_gemm(const float* __restrict__ A,
                                              const float* __restrict__ W,
                                              const float* __restrict__ bias,
                                              float* __restrict__ C,
                                              int layout)
{
    constexpr int N = 1024, K = 1024;
    __shared__ float As[2][128][20];   // [m][k], pad 20 -> conflict-free A frags
    __shared__ float Bs[2][16][136];   // [k][n], pad 136 -> conflict-free B frags

    const int t = threadIdx.x, lane = t & 31, wid = t >> 5;
    const int g = lane >> 2, q = lane & 3;
    const int wm = (wid & 3) * 32;     // warp rows
    const int wn = (wid >> 2) * 64;    // warp cols
    const int bx = blockIdx.x, by = blockIdx.y;

    float c[2][8][4];
    #pragma unroll
    for (int mf = 0; mf < 2; ++mf)
        #pragma unroll
        for (int nf = 0; nf < 8; ++nf)
            #pragma unroll
            for (int i = 0; i < 4; ++i) c[mf][nf][i] = 0.f;

    const int aRow0 = t >> 2,         aK0 = (t & 3) * 4;
    const int aRow1 = (t + 256) >> 2, aK1 = aK0;
    const int bK0 = t >> 5,           bC0 = (t & 31) * 4;
    const int bK1 = (t + 256) >> 5,   bC1 = bC0;

    const float* Abase = A + (size_t)(by * 128) * K;
    const float* Wbase = W + bx * 128;

    float4 pa0 = *(const float4*)(Abase + (size_t)aRow0 * K + aK0);
    float4 pa1 = *(const float4*)(Abase + (size_t)aRow1 * K + aK1);
    float4 pb0 = *(const float4*)(Wbase + (size_t)bK0 * N + bC0);
    float4 pb1 = *(const float4*)(Wbase + (size_t)bK1 * N + bC1);

    // store tile 0
    {
        float4 v;
        v.x = f2tff(pa0.x); v.y = f2tff(pa0.y); v.z = f2tff(pa0.z); v.w = f2tff(pa0.w);
        *(float4*)&As[0][aRow0][aK0] = v;
        v.x = f2tff(pa1.x); v.y = f2tff(pa1.y); v.z = f2tff(pa1.z); v.w = f2tff(pa1.w);
        *(float4*)&As[0][aRow1][aK1] = v;
        v.x = f2tff(pb0.x); v.y = f2tff(pb0.y); v.z = f2tff(pb0.z); v.w = f2tff(pb0.w);
        *(float4*)&Bs[0][bK0][bC0] = v;
        v.x = f2tff(pb1.x); v.y = f2tff(pb1.y); v.z = f2tff(pb1.z); v.w = f2tff(pb1.w);
        *(float4*)&Bs[0][bK1][bC1] = v;
    }
    __syncthreads();

    constexpr int NT = K / 16;  // 64
    for (int kt = 0; kt < NT; ++kt) {
        const int cur = kt & 1;
        const bool more = (kt + 1 < NT);
        if (more) {
            int kb = (kt + 1) * 16;
            pa0 = *(const float4*)(Abase + (size_t)aRow0 * K + kb + aK0);
            pa1 = *(const float4*)(Abase + (size_t)aRow1 * K + kb + aK1);
            pb0 = *(const float4*)(Wbase + (size_t)(kb + bK0) * N + bC0);
            pb1 = *(const float4*)(Wbase + (size_t)(kb + bK1) * N + bC1);
        }

        #pragma unroll
        for (int ks = 0; ks < 2; ++ks) {
            const int k0 = ks * 8;
            unsigned a[2][4];
            #pragma unroll
            for (int mf = 0; mf < 2; ++mf) {
                int r = wm + mf * 16 + g;
                a[mf][0] = __float_as_uint(As[cur][r][k0 + q]);
                a[mf][1] = __float_as_uint(As[cur][r + 8][k0 + q]);
                a[mf][2] = __float_as_uint(As[cur][r][k0 + q + 4]);
                a[mf][3] = __float_as_uint(As[cur][r + 8][k0 + q + 4]);
            }
            #pragma unroll
            for (int nf = 0; nf < 8; ++nf) {
                int col = wn + nf * 8 + g;
                unsigned b0 = __float_as_uint(Bs[cur][k0 + q][col]);
                unsigned b1 = __float_as_uint(Bs[cur][k0 + q + 4][col]);
                #pragma unroll
                for (int mf = 0; mf < 2; ++mf)
                    mma_tf32(c[mf][nf][0], c[mf][nf][1], c[mf][nf][2], c[mf][nf][3],
                             a[mf][0], a[mf][1], a[mf][2], a[mf][3], b0, b1);
            }
        }

        if (more) {
            const int nxt = cur ^ 1;
            float4 v;
            v.x = f2tff(pa0.x); v.y = f2tff(pa0.y); v.z = f2tff(pa0.z); v.w = f2tff(pa0.w);
            *(float4*)&As[nxt][aRow0][aK0] = v;
            v.x = f2tff(pa1.x); v.y = f2tff(pa1.y); v.z = f2tff(pa1.z); v.w = f2tff(pa1.w);
            *(float4*)&As[nxt][aRow1][aK1] = v;
            v.x = f2tff(pb0.x); v.y = f2tff(pb0.y); v.z = f2tff(pb0.z); v.w = f2tff(pb0.w);
            *(float4*)&Bs[nxt][bK0][bC0] = v;
            v.x = f2tff(pb1.x); v.y = f2tff(pb1.y); v.z = f2tff(pb1.z); v.w = f2tff(pb1.w);
            *(float4*)&Bs[nxt][bK1][bC1] = v;
            __syncthreads();
        }
    }

    // epilogue: bias + store
    #pragma unroll
    for (int mf = 0; mf < 2; ++mf) {
        #pragma unroll
        for (int half = 0; half < 2; ++half) {
            int gm = by * 128 + wm + mf * 16 + g + half * 8;
            #pragma unroll
            for (int nf = 0; nf < 8; ++nf) {
                int gn = bx * 128 + wn + nf * 8 + 2 * q;
                float v0 = c[mf][nf][half * 2 + 0] + bias[gn];
                float v1 = c[mf][nf][half * 2 + 1] + bias[gn + 1];
                float2 fv = make_float2(v0, v1);
                if (layout == 0) {
                    *(float2*)&C[(size_t)gm * N + gn] = fv;
                } else {
                    int bb_ = gm >> 11, ss = gm & (S - 1);
                    int hh = gn >> 6, dd = gn & 63;
                    *(float2*)&C[(((size_t)(bb_ * H + hh)) * S + ss) * HD + dd] = fv;
                }
            }
        }
    }
}

// ---------------- fused flash attention (tf32 mma, BM=128) ----------------
// grid (H, B*(S/128)), 256 threads (8 warps); warp w owns query rows [16w,16w+16)
__global__ void __launch_bounds__(256, 2) k_flash(const float* __restrict__ mod)
{
    extern __shared__ float sh[];
    float* Qs = sh;                 // [128][68] tf32
    float* Ks = Qs + 128 * 68;      // [64][68] tf32
    float* Vs = Ks + 64 * 68;       // [64][72] tf32
    float* Ps = Vs + 64 * 72;       // [128][68] tf32

    const int t = threadIdx.x, lane = t & 31, w = t >> 5;
    const int g = lane >> 2, q = lane & 3;
    const int h = blockIdx.x;
    const int by = blockIdx.y;
    const int b = by >> 4, qt = by & 15;   // S/128 = 16 tiles
    const int bh = b * H + h;

    const float* qg = g_q + ((size_t)bh * S + qt * 128) * HD;
    const float* kg = g_k + (size_t)bh * S * HD;
    const float* vg = g_v + (size_t)bh * S * HD;

    // load Q tile (convert to tf32): 128x64 -> 2048 float4
    #pragma unroll
    for (int i = 0; i < 8; ++i) {
        int idx = t + i * 256;
        int r = idx >> 4, cc = (idx & 15) * 4;
        float4 v = *(const float4*)(qg + r * 64 + cc);
        float4 cv;
        cv.x = f2tff(v.x); cv.y = f2tff(v.y); cv.z = f2tff(v.z); cv.w = f2tff(v.w);
        *(float4*)&Qs[r * 68 + cc] = cv;
    }

    const int r0 = w * 16 + g;
    const bool qm0 = g_qmask[b * S + qt * 128 + r0] != 0;
    const bool qm1 = g_qmask[b * S + qt * 128 + r0 + 8] != 0;
    const float* m0p = mod + ((size_t)b * S + qt * 128 + r0) * S;
    const float* m1p = m0p + (size_t)8 * S;

    float o[8][4];
    #pragma unroll
    for (int nf = 0; nf < 8; ++nf)
        #pragma unroll
        for (int i = 0; i < 4; ++i) o[nf][i] = 0.f;
    float mr0 = -1e30f, mr1 = -1e30f, l0 = 0.f, l1 = 0.f;

    __syncthreads();

    for (int nt = 0; nt < S / 64; ++nt) {
        if (nt) __syncthreads();
        // fill K,V tiles: 64x64 each -> 1024 float4 each
        #pragma unroll
        for (int i = 0; i < 4; ++i) {
            int idx = t + i * 256;
            int r = idx >> 4, cc = (idx & 15) * 4;
            float4 kv = *(const float4*)(kg + (size_t)(nt * 64 + r) * 64 + cc);
            float4 vv = *(const float4*)(vg + (size_t)(nt * 64 + r) * 64 + cc);
            float4 c1, c2;
            c1.x = f2tff(kv.x); c1.y = f2tff(kv.y); c1.z = f2tff(kv.z); c1.w = f2tff(kv.w);
            c2.x = f2tff(vv.x); c2.y = f2tff(vv.y); c2.z = f2tff(vv.z); c2.w = f2tff(vv.w);
            *(float4*)&Ks[r * 68 + cc] = c1;
            *(float4*)&Vs[r * 72 + cc] = c2;
        }
        __syncthreads();

        // S = Q @ K^T
        float s[8][4];
        #pragma unroll
        for (int nf = 0; nf < 8; ++nf)
            #pragma unroll
            for (int i = 0; i < 4; ++i) s[nf][i] = 0.f;

        #pragma unroll
        for (int kk = 0; kk < 8; ++kk) {
            const int k0 = kk * 8;
            unsigned a0 = __float_as_uint(Qs[r0 * 68 + k0 + q]);
            unsigned a1 = __float_as_uint(Qs[(r0 + 8) * 68 + k0 + q]);
            unsigned a2 = __float_as_uint(Qs[r0 * 68 + k0 + q + 4]);
            unsigned a3 = __float_as_uint(Qs[(r0 + 8) * 68 + k0 + q + 4]);
            #pragma unroll
            for (int nf = 0; nf < 8; ++nf) {
                unsigned b0 = __float_as_uint(Ks[(nf * 8 + g) * 68 + k0 + q]);
                unsigned b1 = __float_as_uint(Ks[(nf * 8 + g) * 68 + k0 + q + 4]);
                mma_tf32(s[nf][0], s[nf][1], s[nf][2], s[nf][3], a0, a1, a2, a3, b0, b1);
            }
        }

        // modifier * scale, query-axis mask, online softmax
        float mx0 = -1e30f, mx1 = -1e30f;
        #pragma unroll
        for (int nf = 0; nf < 8; ++nf) {
            float2 md0 = *(const float2*)(m0p + nt * 64 + nf * 8 + 2 * q);
            float2 md1 = *(const float2*)(m1p + nt * 64 + nf * 8 + 2 * q);
            s[nf][0] = qm0 ? -1e10f : s[nf][0] * 0.125f * md0.x;
            s[nf][1] = qm0 ? -1e10f : s[nf][1] * 0.125f * md0.y;
            s[nf][2] = qm1 ? -1e10f : s[nf][2] * 0.125f * md1.x;
            s[nf][3] = qm1 ? -1e10f : s[nf][3] * 0.125f * md1.y;
            mx0 = fmaxf(mx0, fmaxf(s[nf][0], s[nf][1]));
            mx1 = fmaxf(mx1, fmaxf(s[nf][2], s[nf][3]));
        }
        mx0 = fmaxf(mx0, __shfl_xor_sync(0xffffffffu, mx0, 1));
        mx0 = fmaxf(mx0, __shfl_xor_sync(0xffffffffu, mx0, 2));
        mx1 = fmaxf(mx1, __shfl_xor_sync(0xffffffffu, mx1, 1));
        mx1 = fmaxf(mx1, __shfl_xor_sync(0xffffffffu, mx1, 2));

        float mn0 = fmaxf(mr0, mx0), mn1 = fmaxf(mr1, mx1);
        float co0 = __expf(mr0 - mn0), co1 = __expf(mr1 - mn1);
        float rs0 = 0.f, rs1 = 0.f;
        #pragma unroll
        for (int nf = 0; nf < 8; ++nf) {
            float p0 = __expf(s[nf][0] - mn0);
            float p1 = __expf(s[nf][1] - mn0);
            float p2 = __expf(s[nf][2] - mn1);
            float p3 = __expf(s[nf][3] - mn1);
            rs0 += p0 + p1; rs1 += p2 + p3;
            *(float2*)&Ps[r0 * 68 + nf * 8 + 2 * q]       = make_float2(f2tff(p0), f2tff(p1));
            *(float2*)&Ps[(r0 + 8) * 68 + nf * 8 + 2 * q] = make_float2(f2tff(p2), f2tff(p3));
        }
        rs0 += __shfl_xor_sync(0xffffffffu, rs0, 1);
        rs0 += __shfl_xor_sync(0xffffffffu, rs0, 2);
        rs1 += __shfl_xor_sync(0xffffffffu, rs1, 1);
        rs1 += __shfl_xor_sync(0xffffffffu, rs1, 2);
        l0 = l0 * co0 + rs0;
        l1 = l1 * co1 + rs1;
        mr0 = mn0; mr1 = mn1;
        #pragma unroll
        for (int nf = 0; nf < 8; ++nf) {
            o[nf][0] *= co0; o[nf][1] *= co0;
            o[nf][2] *= co1; o[nf][3] *= co1;
        }
        __syncwarp();

        // O += P @ V   (Ps rows of this warp written only by this warp)
        #pragma unroll
        for (int kk = 0; kk < 8; ++kk) {
            const int k0 = kk * 8;
            unsigned a0 = __float_as_uint(Ps[r0 * 68 + k0 + q]);
            unsigned a1 = __float_as_uint(Ps[(r0 + 8) * 68 + k0 + q]);
            unsigned a2 = __float_as_uint(Ps[r0 * 68 + k0 + q + 4]);
            unsigned a3 = __float_as_uint(Ps[(r0 + 8) * 68 + k0 + q + 4]);
            #pragma unroll
            for (int nf = 0; nf < 8; ++nf) {
                unsigned b0 = __float_as_uint(Vs[(k0 + q) * 72 + nf * 8 + g]);
                unsigned b1 = __float_as_uint(Vs[(k0 + q + 4) * 72 + nf * 8 + g]);
                mma_tf32(o[nf][0], o[nf][1], o[nf][2], o[nf][3], a0, a1, a2, a3, b0, b1);
            }
        }
    }

    // normalize, write [B,S,D]
    float i0 = 1.0f / l0, i1 = 1.0f / l1;
    float* ob = g_att + ((size_t)b * S + qt * 128) * D + h * 64;
    #pragma unroll
    for (int nf = 0; nf < 8; ++nf) {
        *(float2*)&ob[(size_t)r0 * D + nf * 8 + 2 * q] =
            make_float2(o[nf][0] * i0, o[nf][1] * i0);
        *(float2*)&ob[(size_t)(r0 + 8) * D + nf * 8 + 2 * q] =
            make_float2(o[nf][2] * i1, o[nf][3] * i1);
    }
}

// ---------------- launch ----------------
extern "C" void kernel_launch(void* const* d_in, const int* in_sizes, int n_in,
                              void* d_out, int out_size)
{
    const float* x   = (const float*)d_in[0];
    const void*  kpm = d_in[1];
    const float* mod = (const float*)d_in[2];
    const float* Wq  = (const float*)d_in[3];
    const float* bq  = (const float*)d_in[4];
    const float* Wk  = (const float*)d_in[5];
    const float* bk  = (const float*)d_in[6];
    const float* Wv  = (const float*)d_in[7];
    const float* bv  = (const float*)d_in[8];
    const float* Wo  = (const float*)d_in[9];
    const float* bo  = (const float*)d_in[10];
    float* out = (float*)d_out;

    float *qp, *kp, *vp, *ap;
    cudaGetSymbolAddress((void**)&qp, g_q);
    cudaGetSymbolAddress((void**)&kp, g_k);
    cudaGetSymbolAddress((void**)&vp, g_v);
    cudaGetSymbolAddress((void**)&ap, g_att);

    k_init_sig<<<1, 1>>>();
    k_detect<<<(B * S + 255) / 256, 256>>>((const unsigned char*)kpm);
    k_convert<<<(B * S + 255) / 256, 256>>>(kpm);

    dim3 gg(D / 128, M / 128);
    k_gemm<<<gg, 256>>>(x, Wq, bq, qp, 1);
    k_gemm<<<gg, 256>>>(x, Wk, bk, kp, 1);
    k_gemm<<<gg, 256>>>(x, Wv, bv, vp, 1);

    constexpr int SMEM = (128 * 68 + 64 * 68 + 64 * 72 + 128 * 68) * 4;  // 105472 B
    cudaFuncSetAttribute(k_flash, cudaFuncAttributeMaxDynamicSharedMemorySize, SMEM);
    k_flash<<<dim3(H, B * (S / 128)), 256, SMEM>>>(mod);

    k_gemm<<<gg, 256>>>(ap, Wo, bo, out, 0);
}